// round 5
// baseline (speedup 1.0000x reference)
#include <cuda_runtime.h>
#include <math.h>

#define MAXN 100000
#define MAXE 1000000
#define MAXG 128
#define HDIM 64

// ---------------- device scratch (no allocations allowed) ----------------
__device__ float g_x[MAXN * HDIM];      // current node features
__device__ float g_t[MAXN * HDIM];      // x + aggregated neighbors (conv MLP input)
__device__ int   g_indeg[MAXN + 1];
__device__ int   g_off[MAXN + 1];       // CSR row offsets (by dst)
__device__ int   g_cursor[MAXN];        // scan temp + fill cursors
__device__ int   g_csr[MAXE];           // src node per CSR slot
__device__ int   g_bsum[1024];          // scan block sums
__device__ float g_pooled[4 * MAXG * HDIM];
__device__ int   g_cnt[MAXG];

// ---------------- trivial kernels ----------------
__global__ void k_zero(int n_indeg) {
    int i = blockIdx.x * blockDim.x + threadIdx.x;
    if (i < 4 * MAXG * HDIM) g_pooled[i] = 0.f;
    if (i < MAXG) g_cnt[i] = 0;
    if (i < n_indeg) g_indeg[i] = 0;
}

__global__ void k_count(const int* __restrict__ dst, int E) {
    int e = blockIdx.x * blockDim.x + threadIdx.x;
    if (e < E) atomicAdd(&g_indeg[dst[e]], 1);
}

// per-block inclusive scan of g_indeg -> g_cursor (local incl) + g_bsum
__global__ void k_scan1(int n) {
    __shared__ int s[1024];
    int i = blockIdx.x * 1024 + threadIdx.x;
    int v = (i < n) ? g_indeg[i] : 0;
    s[threadIdx.x] = v;
    __syncthreads();
    for (int d = 1; d < 1024; d <<= 1) {
        int t = (threadIdx.x >= d) ? s[threadIdx.x - d] : 0;
        __syncthreads();
        s[threadIdx.x] += t;
        __syncthreads();
    }
    if (i < n) g_cursor[i] = s[threadIdx.x];
    if (threadIdx.x == 1023) g_bsum[blockIdx.x] = s[1023];
}

__global__ void k_scan2(int nb) {
    __shared__ int s[1024];
    int v = (threadIdx.x < nb) ? g_bsum[threadIdx.x] : 0;
    s[threadIdx.x] = v;
    __syncthreads();
    for (int d = 1; d < 1024; d <<= 1) {
        int t = (threadIdx.x >= d) ? s[threadIdx.x - d] : 0;
        __syncthreads();
        s[threadIdx.x] += t;
        __syncthreads();
    }
    if (threadIdx.x < nb) g_bsum[threadIdx.x] = s[threadIdx.x];
}

__global__ void k_scan3(int n, int nb) {
    int i = blockIdx.x * blockDim.x + threadIdx.x;
    if (i < n) {
        int blk = i >> 10;
        int pref = (blk > 0) ? g_bsum[blk - 1] : 0;
        int excl = g_cursor[i] - g_indeg[i] + pref;
        g_off[i] = excl;
        g_cursor[i] = excl;
    }
    if (i == 0) g_off[n] = g_bsum[nb - 1];
}

__global__ void k_fill(const int* __restrict__ src, const int* __restrict__ dst, int E) {
    int e = blockIdx.x * blockDim.x + threadIdx.x;
    if (e < E) {
        int pos = atomicAdd(&g_cursor[dst[e]], 1);
        g_csr[pos] = src[e];
    }
}

__global__ void k_cnt(const int* __restrict__ batch, int N) {
    int i = blockIdx.x * blockDim.x + threadIdx.x;
    if (i < N) atomicAdd(&g_cnt[batch[i]], 1);
}

// ---------------- aggregation: g_t[n] = g_x[n] + sum_{src->n} g_x[src] ----------------
__global__ void k_agg(int N) {
    int w = (blockIdx.x * blockDim.x + threadIdx.x) >> 5;
    int lane = threadIdx.x & 31;
    if (w >= N) return;
    const float2* xb = (const float2*)g_x;
    float2 acc = xb[(size_t)w * 32 + lane];
    int s = g_off[w], e = g_off[w + 1];
    for (int i = s; i < e; i++) {
        int sn = __ldg(&g_csr[i]);
        float2 v = __ldg(&xb[(size_t)sn * 32 + lane]);
        acc.x += v.x; acc.y += v.y;
    }
    ((float2*)g_t)[(size_t)w * 32 + lane] = acc;
}

// ---------------- fused 2-layer MLP (+BN-fold+ReLU) + sum-pool ----------------
// Block: 256 threads, tile 64 nodes x 64 features, 4x4 register micro-tile.
template <int IN, bool EMBED>
__global__ void __launch_bounds__(256) k_mlp(
    const float* __restrict__ emb, const int* __restrict__ node_ids,
    const float* __restrict__ W1, const float* __restrict__ B1,
    const float* __restrict__ G1, const float* __restrict__ BT1,
    const float* __restrict__ M1, const float* __restrict__ V1,
    const float* __restrict__ W2, const float* __restrict__ B2,
    const float* __restrict__ G2, const float* __restrict__ BT2,
    const float* __restrict__ M2, const float* __restrict__ V2,
    const int* __restrict__ batch, int poolIdx, int N)
{
    extern __shared__ float sm[];
    float* W1s = sm;                 // IN*64
    float* W2s = W1s + IN * 64;      // 64*64
    float* Xs  = W2s + 64 * 64;      // IN*68 (transposed [k][node], pad 68)
    float* Hs  = Xs + IN * 68;       // 64*68
    float* sc1 = Hs + 64 * 68;
    float* of1 = sc1 + 64;
    float* sc2 = of1 + 64;
    float* of2 = sc2 + 64;

    int tid = threadIdx.x;
    int base = blockIdx.x * 64;

    for (int i = tid; i < IN * 64; i += 256) W1s[i] = W1[i];
    for (int i = tid; i < 64 * 64; i += 256) W2s[i] = W2[i];
    if (tid < 64) {
        float s = G1[tid] * rsqrtf(V1[tid] + 1e-5f);
        sc1[tid] = s;
        of1[tid] = B1[tid] * s + BT1[tid] - M1[tid] * s;
        float s2 = G2[tid] * rsqrtf(V2[tid] + 1e-5f);
        sc2[tid] = s2;
        of2[tid] = B2[tid] * s2 + BT2[tid] - M2[tid] * s2;
    }

    // stage input tile transposed into Xs[k][n]
    {
        int n = tid >> 2, q = tid & 3;
        int node = base + n;
        if (EMBED) {
            const float4* row = (node < N)
                ? (const float4*)(emb + (size_t)__ldg(&node_ids[node]) * 128) : 0;
#pragma unroll
            for (int i = 0; i < 8; i++) {
                float4 v = make_float4(0.f, 0.f, 0.f, 0.f);
                if (node < N) v = __ldg(&row[q * 8 + i]);
                int k = (q * 8 + i) * 4;
                Xs[(k + 0) * 68 + n] = v.x;
                Xs[(k + 1) * 68 + n] = v.y;
                Xs[(k + 2) * 68 + n] = v.z;
                Xs[(k + 3) * 68 + n] = v.w;
            }
        } else {
            const float4* row = (const float4*)(g_t + (size_t)node * 64);
#pragma unroll
            for (int i = 0; i < 4; i++) {
                float4 v = make_float4(0.f, 0.f, 0.f, 0.f);
                if (node < N) v = row[q * 4 + i];
                int k = (q * 4 + i) * 4;
                Xs[(k + 0) * 68 + n] = v.x;
                Xs[(k + 1) * 68 + n] = v.y;
                Xs[(k + 2) * 68 + n] = v.z;
                Xs[(k + 3) * 68 + n] = v.w;
            }
        }
    }
    __syncthreads();

    int tj = tid & 15, tn = tid >> 4;
    int nb = tn * 4, jb = tj * 4;
    float acc[4][4];
#pragma unroll
    for (int u = 0; u < 4; u++)
#pragma unroll
        for (int v = 0; v < 4; v++) acc[u][v] = 0.f;

    // layer 1: [64 x IN] @ [IN x 64]
    for (int k = 0; k < IN; k++) {
        float4 a = *(const float4*)(Xs + k * 68 + nb);
        float4 b = *(const float4*)(W1s + k * 64 + jb);
        float av[4] = {a.x, a.y, a.z, a.w};
        float bv[4] = {b.x, b.y, b.z, b.w};
#pragma unroll
        for (int u = 0; u < 4; u++)
#pragma unroll
            for (int v = 0; v < 4; v++) acc[u][v] = fmaf(av[u], bv[v], acc[u][v]);
    }
    // BN+ReLU -> Hs transposed [j][node]
#pragma unroll
    for (int v = 0; v < 4; v++) {
        float s = sc1[jb + v], o = of1[jb + v];
#pragma unroll
        for (int u = 0; u < 4; u++) {
            float h = fmaf(acc[u][v], s, o);
            Hs[(jb + v) * 68 + nb + u] = fmaxf(h, 0.f);
            acc[u][v] = 0.f;
        }
    }
    __syncthreads();

    // layer 2: [64 x 64] @ [64 x 64]
    for (int k = 0; k < 64; k++) {
        float4 a = *(const float4*)(Hs + k * 68 + nb);
        float4 b = *(const float4*)(W2s + k * 64 + jb);
        float av[4] = {a.x, a.y, a.z, a.w};
        float bv[4] = {b.x, b.y, b.z, b.w};
#pragma unroll
        for (int u = 0; u < 4; u++)
#pragma unroll
            for (int v = 0; v < 4; v++) acc[u][v] = fmaf(av[u], bv[v], acc[u][v]);
    }
    __syncthreads();  // all Hs reads done; reuse as output staging [n][j]

    float* Os = Hs;
#pragma unroll
    for (int v = 0; v < 4; v++) {
        float s = sc2[jb + v], o = of2[jb + v];
#pragma unroll
        for (int u = 0; u < 4; u++) {
            float h = fmaf(acc[u][v], s, o);
            Os[(nb + u) * 68 + jb + v] = fmaxf(h, 0.f);
        }
    }
    __syncthreads();

    // write out coalesced
    {
        int n = tid >> 2, q = tid & 3;
        int node = base + n;
        if (node < N) {
#pragma unroll
            for (int i = 0; i < 4; i++) {
                float4 vv = *(const float4*)(Os + n * 68 + q * 16 + i * 4);
                *(float4*)(g_x + (size_t)node * 64 + q * 16 + i * 4) = vv;
            }
        }
    }

    // fused sum-pool (batch is sorted: most blocks lie in one graph)
    float* pool = g_pooled + poolIdx * (MAXG * HDIM);
    int lastnode = min(base + 63, N - 1);
    int bF = batch[base];
    int bL = batch[lastnode];
    if (bF == bL && base + 63 < N) {
        if (tid < 64) {
            float ssum = 0.f;
#pragma unroll 8
            for (int n2 = 0; n2 < 64; n2++) ssum += Os[n2 * 68 + tid];
            atomicAdd(&pool[bF * 64 + tid], ssum);
        }
    } else {
        if (tid < 64) {
            for (int n2 = 0; n2 < 64; n2++) {
                int node = base + n2;
                if (node < N) atomicAdd(&pool[batch[node] * 64 + tid], Os[n2 * 68 + tid]);
            }
        }
    }
}

// ---------------- final: per-graph logits + softmax ----------------
__global__ void k_final(const float* __restrict__ lin_W, const float* __restrict__ lin_b,
                        float* __restrict__ out, int G)
{
    int g = threadIdx.x;
    if (g >= G) return;
    double l0 = 0.0, l1 = 0.0;
    for (int p = 0; p < 4; p++) {
        const float* pw = lin_W + p * 128;           // [64][2]
        const float* pv = g_pooled + p * (MAXG * HDIM) + g * 64;
        for (int k = 0; k < 64; k++) {
            float v = pv[k];
            l0 += (double)v * pw[k * 2 + 0];
            l1 += (double)v * pw[k * 2 + 1];
        }
    }
    double c = (double)g_cnt[g];
    l0 += c * lin_b[0] + lin_b[2] + lin_b[4] + lin_b[6];
    l1 += c * lin_b[1] + lin_b[3] + lin_b[5] + lin_b[7];
    float f0 = (float)l0, f1 = (float)l1;
    float m = fmaxf(f0, f1);
    float e0 = expf(f0 - m), e1 = expf(f1 - m);
    float inv = 1.f / (e0 + e1);
    out[g * 2 + 0] = e0 * inv;
    out[g * 2 + 1] = e1 * inv;
}

// ---------------- launch ----------------
extern "C" void kernel_launch(void* const* d_in, const int* in_sizes, int n_in,
                              void* d_out, int out_size)
{
    const int*   node_ids = (const int*)d_in[0];
    const int*   edge     = (const int*)d_in[1];
    const int*   batch    = (const int*)d_in[2];
    const float* emb      = (const float*)d_in[3];
    const float* fh_W1 = (const float*)d_in[4];
    const float* fh_b1 = (const float*)d_in[5];
    const float* fh_g1 = (const float*)d_in[6];
    const float* fh_bt1 = (const float*)d_in[7];
    const float* fh_m1 = (const float*)d_in[8];
    const float* fh_v1 = (const float*)d_in[9];
    const float* fh_W2 = (const float*)d_in[10];
    const float* fh_b2 = (const float*)d_in[11];
    const float* fh_g2 = (const float*)d_in[12];
    const float* fh_bt2 = (const float*)d_in[13];
    const float* fh_m2 = (const float*)d_in[14];
    const float* fh_v2 = (const float*)d_in[15];
    const float* conv_W1 = (const float*)d_in[16];
    const float* conv_b1 = (const float*)d_in[17];
    const float* conv_g1 = (const float*)d_in[18];
    const float* conv_bt1 = (const float*)d_in[19];
    const float* conv_m1 = (const float*)d_in[20];
    const float* conv_v1 = (const float*)d_in[21];
    const float* conv_W2 = (const float*)d_in[22];
    const float* conv_b2 = (const float*)d_in[23];
    const float* conv_g2 = (const float*)d_in[24];
    const float* conv_bt2 = (const float*)d_in[25];
    const float* conv_m2 = (const float*)d_in[26];
    const float* conv_v2 = (const float*)d_in[27];
    const float* lin_W = (const float*)d_in[28];
    const float* lin_b = (const float*)d_in[29];

    int N = in_sizes[0];
    int E = in_sizes[1] / 2;
    int G = out_size / 2;
    const int* src = edge;
    const int* dst = edge + E;

    const int SMEM_EMB  = (128 * 64 + 64 * 64 + 128 * 68 + 64 * 68 + 256) * 4;  // 102400
    const int SMEM_CONV = (64 * 64 + 64 * 64 + 64 * 68 + 64 * 68 + 256) * 4;    // 68608
    cudaFuncSetAttribute((const void*)k_mlp<128, true>,
                         cudaFuncAttributeMaxDynamicSharedMemorySize, SMEM_EMB);
    cudaFuncSetAttribute((const void*)k_mlp<64, false>,
                         cudaFuncAttributeMaxDynamicSharedMemorySize, SMEM_CONV);

    // zero accumulators + degree counters
    int zn = (4 * MAXG * HDIM > N + 1) ? 4 * MAXG * HDIM : N + 1;
    k_zero<<<(zn + 255) / 256, 256>>>(N + 1);

    // CSR build (reused for all 3 conv layers)
    k_count<<<(E + 255) / 256, 256>>>(dst, E);
    int nb = (N + 1023) / 1024;
    k_scan1<<<nb, 1024>>>(N);
    k_scan2<<<1, 1024>>>(nb);
    k_scan3<<<(N + 255) / 256, 256>>>(N, nb);
    k_fill<<<(E + 255) / 256, 256>>>(src, dst, E);
    k_cnt<<<(N + 255) / 256, 256>>>(batch, N);

    int mblocks = (N + 63) / 64;

    // embedding gather + feature MLP + pool[0]
    k_mlp<128, true><<<mblocks, 256, SMEM_EMB>>>(
        emb, node_ids,
        fh_W1, fh_b1, fh_g1, fh_bt1, fh_m1, fh_v1,
        fh_W2, fh_b2, fh_g2, fh_bt2, fh_m2, fh_v2,
        batch, 0, N);

    // 3 GINConv layers
    for (int l = 0; l < 3; l++) {
        k_agg<<<(N + 7) / 8, 256>>>(N);
        k_mlp<64, false><<<mblocks, 256, SMEM_CONV>>>(
            nullptr, nullptr,
            conv_W1 + l * 4096, conv_b1 + l * 64, conv_g1 + l * 64, conv_bt1 + l * 64,
            conv_m1 + l * 64, conv_v1 + l * 64,
            conv_W2 + l * 4096, conv_b2 + l * 64, conv_g2 + l * 64, conv_bt2 + l * 64,
            conv_m2 + l * 64, conv_v2 + l * 64,
            batch, l + 1, N);
    }

    k_final<<<1, 128>>>(lin_W, lin_b, (float*)d_out, G);
}

// round 9
// speedup vs baseline: 1.0061x; 1.0061x over previous
#include <cuda_runtime.h>
#include <math.h>

#define MAXN 100000
#define MAXE 1000000
#define MAXG 128
#define HDIM 64

typedef unsigned long long u64;

// ---------------- f32x2 packed helpers (sm_100-family PTX, not 'a'-gated) ----------------
__device__ __forceinline__ u64 pack2(float lo, float hi) {
    u64 r; asm("mov.b64 %0, {%1, %2};" : "=l"(r) : "f"(lo), "f"(hi)); return r;
}
__device__ __forceinline__ void unpack2(float& lo, float& hi, u64 v) {
    asm("mov.b64 {%0, %1}, %2;" : "=f"(lo), "=f"(hi) : "l"(v));
}
__device__ __forceinline__ void fma2(u64& acc, u64 a, u64 b) {
    asm("fma.rn.f32x2 %0, %1, %2, %0;" : "+l"(acc) : "l"(a), "l"(b));
}

// ---------------- device scratch (no allocations allowed) ----------------
__device__ float g_x[MAXN * HDIM];      // current node features
__device__ float g_t[MAXN * HDIM];      // x + aggregated neighbors (conv MLP input)
__device__ int   g_indeg[MAXN + 1];
__device__ int   g_off[MAXN + 1];       // CSR row offsets (by dst)
__device__ int   g_cursor[MAXN];        // scan temp + fill cursors
__device__ int   g_csr[MAXE];           // src node per CSR slot
__device__ int   g_bsum[1024];          // scan block sums
__device__ float g_pooled[4 * MAXG * HDIM];
__device__ int   g_cnt[MAXG];

// ---------------- trivial kernels ----------------
__global__ void k_zero(int n_indeg) {
    int i = blockIdx.x * blockDim.x + threadIdx.x;
    if (i < 4 * MAXG * HDIM) g_pooled[i] = 0.f;
    if (i < MAXG) g_cnt[i] = 0;
    if (i < n_indeg) g_indeg[i] = 0;
}

__global__ void k_count(const int* __restrict__ dst, int E) {
    int e = blockIdx.x * blockDim.x + threadIdx.x;
    if (e < E) atomicAdd(&g_indeg[dst[e]], 1);
}

__global__ void k_scan1(int n) {
    __shared__ int s[1024];
    int i = blockIdx.x * 1024 + threadIdx.x;
    int v = (i < n) ? g_indeg[i] : 0;
    s[threadIdx.x] = v;
    __syncthreads();
    for (int d = 1; d < 1024; d <<= 1) {
        int t = (threadIdx.x >= d) ? s[threadIdx.x - d] : 0;
        __syncthreads();
        s[threadIdx.x] += t;
        __syncthreads();
    }
    if (i < n) g_cursor[i] = s[threadIdx.x];
    if (threadIdx.x == 1023) g_bsum[blockIdx.x] = s[1023];
}

__global__ void k_scan2(int nb) {
    __shared__ int s[1024];
    int v = (threadIdx.x < nb) ? g_bsum[threadIdx.x] : 0;
    s[threadIdx.x] = v;
    __syncthreads();
    for (int d = 1; d < 1024; d <<= 1) {
        int t = (threadIdx.x >= d) ? s[threadIdx.x - d] : 0;
        __syncthreads();
        s[threadIdx.x] += t;
        __syncthreads();
    }
    if (threadIdx.x < nb) g_bsum[threadIdx.x] = s[threadIdx.x];
}

__global__ void k_scan3(int n, int nb) {
    int i = blockIdx.x * blockDim.x + threadIdx.x;
    if (i < n) {
        int blk = i >> 10;
        int pref = (blk > 0) ? g_bsum[blk - 1] : 0;
        int excl = g_cursor[i] - g_indeg[i] + pref;
        g_off[i] = excl;
        g_cursor[i] = excl;
    }
    if (i == 0) g_off[n] = g_bsum[nb - 1];
}

__global__ void k_fill(const int* __restrict__ src, const int* __restrict__ dst, int E) {
    int e = blockIdx.x * blockDim.x + threadIdx.x;
    if (e < E) {
        int pos = atomicAdd(&g_cursor[dst[e]], 1);
        g_csr[pos] = src[e];
    }
}

__global__ void k_cnt(const int* __restrict__ batch, int N) {
    int i = blockIdx.x * blockDim.x + threadIdx.x;
    if (i < N) atomicAdd(&g_cnt[batch[i]], 1);
}

// ---------------- aggregation: g_t[n] = g_x[n] + sum_{src->n} g_x[src] ----------------
__global__ void k_agg(int N) {
    int w = (blockIdx.x * blockDim.x + threadIdx.x) >> 5;
    int lane = threadIdx.x & 31;
    if (w >= N) return;
    const float2* xb = (const float2*)g_x;
    float2 acc = xb[(size_t)w * 32 + lane];
    int s = g_off[w], e = g_off[w + 1];
    for (int i = s; i < e; i++) {
        int sn = __ldg(&g_csr[i]);
        float2 v = __ldg(&xb[(size_t)sn * 32 + lane]);
        acc.x += v.x; acc.y += v.y;
    }
    ((float2*)g_t)[(size_t)w * 32 + lane] = acc;
}

// ---------------- fused 2-layer MLP (+BN-fold+ReLU) + sum-pool, FFMA2 inner loops ----------------
// Block: 256 threads, tile 64 nodes x 64 features, 4x4 register micro-tile packed as 4x(2x2).
template <int IN, bool EMBED>
__global__ void __launch_bounds__(256) k_mlp(
    const float* __restrict__ emb, const int* __restrict__ node_ids,
    const float* __restrict__ W1, const float* __restrict__ B1,
    const float* __restrict__ G1, const float* __restrict__ BT1,
    const float* __restrict__ M1, const float* __restrict__ V1,
    const float* __restrict__ W2, const float* __restrict__ B2,
    const float* __restrict__ G2, const float* __restrict__ BT2,
    const float* __restrict__ M2, const float* __restrict__ V2,
    const int* __restrict__ batch, int poolIdx, int N)
{
    extern __shared__ float sm[];
    float* W1s = sm;                 // IN*64
    float* W2s = W1s + IN * 64;      // 64*64
    float* Xs  = W2s + 64 * 64;      // IN*68 (transposed [k][node], pad 68)
    float* Hs  = Xs + IN * 68;       // 64*68
    float* sc1 = Hs + 64 * 68;
    float* of1 = sc1 + 64;
    float* sc2 = of1 + 64;
    float* of2 = sc2 + 64;

    int tid = threadIdx.x;
    int base = blockIdx.x * 64;

    for (int i = tid; i < IN * 64; i += 256) W1s[i] = W1[i];
    for (int i = tid; i < 64 * 64; i += 256) W2s[i] = W2[i];
    if (tid < 64) {
        float s = G1[tid] * rsqrtf(V1[tid] + 1e-5f);
        sc1[tid] = s;
        of1[tid] = B1[tid] * s + BT1[tid] - M1[tid] * s;
        float s2 = G2[tid] * rsqrtf(V2[tid] + 1e-5f);
        sc2[tid] = s2;
        of2[tid] = B2[tid] * s2 + BT2[tid] - M2[tid] * s2;
    }

    // stage input tile transposed into Xs[k][n]
    {
        int n = tid >> 2, q = tid & 3;
        int node = base + n;
        if (EMBED) {
            const float4* row = (node < N)
                ? (const float4*)(emb + (size_t)__ldg(&node_ids[node]) * 128) : 0;
#pragma unroll
            for (int i = 0; i < 8; i++) {
                float4 v = make_float4(0.f, 0.f, 0.f, 0.f);
                if (node < N) v = __ldg(&row[q * 8 + i]);
                int k = (q * 8 + i) * 4;
                Xs[(k + 0) * 68 + n] = v.x;
                Xs[(k + 1) * 68 + n] = v.y;
                Xs[(k + 2) * 68 + n] = v.z;
                Xs[(k + 3) * 68 + n] = v.w;
            }
        } else {
            const float4* row = (const float4*)(g_t + (size_t)node * 64);
#pragma unroll
            for (int i = 0; i < 4; i++) {
                float4 v = make_float4(0.f, 0.f, 0.f, 0.f);
                if (node < N) v = row[q * 4 + i];
                int k = (q * 4 + i) * 4;
                Xs[(k + 0) * 68 + n] = v.x;
                Xs[(k + 1) * 68 + n] = v.y;
                Xs[(k + 2) * 68 + n] = v.z;
                Xs[(k + 3) * 68 + n] = v.w;
            }
        }
    }
    __syncthreads();

    int tj = tid & 15, tn = tid >> 4;
    int nb = tn * 4, jb = tj * 4;
    // packed accumulators: acc2[u][p] = (out[jb+2p], out[jb+2p+1]) for node nb+u
    u64 acc2[4][2];
#pragma unroll
    for (int u = 0; u < 4; u++) { acc2[u][0] = 0ULL; acc2[u][1] = 0ULL; }

    // layer 1: [64 x IN] @ [IN x 64]
#pragma unroll 4
    for (int k = 0; k < IN; k++) {
        float4 a = *(const float4*)(Xs + k * 68 + nb);
        float4 b = *(const float4*)(W1s + k * 64 + jb);
        u64 b0 = pack2(b.x, b.y), b1 = pack2(b.z, b.w);
        u64 a0 = pack2(a.x, a.x), a1 = pack2(a.y, a.y);
        u64 a2 = pack2(a.z, a.z), a3 = pack2(a.w, a.w);
        fma2(acc2[0][0], a0, b0); fma2(acc2[0][1], a0, b1);
        fma2(acc2[1][0], a1, b0); fma2(acc2[1][1], a1, b1);
        fma2(acc2[2][0], a2, b0); fma2(acc2[2][1], a2, b1);
        fma2(acc2[3][0], a3, b0); fma2(acc2[3][1], a3, b1);
    }
    // BN+ReLU -> Hs transposed [j][node]
#pragma unroll
    for (int p = 0; p < 2; p++) {
        float s0 = sc1[jb + 2 * p], o0 = of1[jb + 2 * p];
        float s1 = sc1[jb + 2 * p + 1], o1 = of1[jb + 2 * p + 1];
#pragma unroll
        for (int u = 0; u < 4; u++) {
            float lo, hi;
            unpack2(lo, hi, acc2[u][p]);
            Hs[(jb + 2 * p) * 68 + nb + u]     = fmaxf(fmaf(lo, s0, o0), 0.f);
            Hs[(jb + 2 * p + 1) * 68 + nb + u] = fmaxf(fmaf(hi, s1, o1), 0.f);
            acc2[u][p] = 0ULL;
        }
    }
    __syncthreads();

    // layer 2: [64 x 64] @ [64 x 64]
#pragma unroll 4
    for (int k = 0; k < 64; k++) {
        float4 a = *(const float4*)(Hs + k * 68 + nb);
        float4 b = *(const float4*)(W2s + k * 64 + jb);
        u64 b0 = pack2(b.x, b.y), b1 = pack2(b.z, b.w);
        u64 a0 = pack2(a.x, a.x), a1 = pack2(a.y, a.y);
        u64 a2 = pack2(a.z, a.z), a3 = pack2(a.w, a.w);
        fma2(acc2[0][0], a0, b0); fma2(acc2[0][1], a0, b1);
        fma2(acc2[1][0], a1, b0); fma2(acc2[1][1], a1, b1);
        fma2(acc2[2][0], a2, b0); fma2(acc2[2][1], a2, b1);
        fma2(acc2[3][0], a3, b0); fma2(acc2[3][1], a3, b1);
    }
    __syncthreads();  // all Hs reads done; reuse as output staging [n][j]

    float* Os = Hs;
#pragma unroll
    for (int p = 0; p < 2; p++) {
        float s0 = sc2[jb + 2 * p], o0 = of2[jb + 2 * p];
        float s1 = sc2[jb + 2 * p + 1], o1 = of2[jb + 2 * p + 1];
#pragma unroll
        for (int u = 0; u < 4; u++) {
            float lo, hi;
            unpack2(lo, hi, acc2[u][p]);
            Os[(nb + u) * 68 + jb + 2 * p]     = fmaxf(fmaf(lo, s0, o0), 0.f);
            Os[(nb + u) * 68 + jb + 2 * p + 1] = fmaxf(fmaf(hi, s1, o1), 0.f);
        }
    }
    __syncthreads();

    // write out coalesced
    {
        int n = tid >> 2, q = tid & 3;
        int node = base + n;
        if (node < N) {
#pragma unroll
            for (int i = 0; i < 4; i++) {
                float4 vv = *(const float4*)(Os + n * 68 + q * 16 + i * 4);
                *(float4*)(g_x + (size_t)node * 64 + q * 16 + i * 4) = vv;
            }
        }
    }

    // fused sum-pool (batch is sorted: most blocks lie in one graph)
    float* pool = g_pooled + poolIdx * (MAXG * HDIM);
    int lastnode = min(base + 63, N - 1);
    int bF = batch[base];
    int bL = batch[lastnode];
    if (bF == bL && base + 63 < N) {
        if (tid < 64) {
            float ssum = 0.f;
#pragma unroll 8
            for (int n2 = 0; n2 < 64; n2++) ssum += Os[n2 * 68 + tid];
            atomicAdd(&pool[bF * 64 + tid], ssum);
        }
    } else {
        if (tid < 64) {
            for (int n2 = 0; n2 < 64; n2++) {
                int node = base + n2;
                if (node < N) atomicAdd(&pool[batch[node] * 64 + tid], Os[n2 * 68 + tid]);
            }
        }
    }
}

// ---------------- final: per-graph logits + softmax ----------------
__global__ void k_final(const float* __restrict__ lin_W, const float* __restrict__ lin_b,
                        float* __restrict__ out, int G)
{
    int g = threadIdx.x;
    if (g >= G) return;
    double l0 = 0.0, l1 = 0.0;
    for (int p = 0; p < 4; p++) {
        const float* pw = lin_W + p * 128;           // [64][2]
        const float* pv = g_pooled + p * (MAXG * HDIM) + g * 64;
        for (int k = 0; k < 64; k++) {
            float v = pv[k];
            l0 += (double)v * pw[k * 2 + 0];
            l1 += (double)v * pw[k * 2 + 1];
        }
    }
    double c = (double)g_cnt[g];
    l0 += c * lin_b[0] + lin_b[2] + lin_b[4] + lin_b[6];
    l1 += c * lin_b[1] + lin_b[3] + lin_b[5] + lin_b[7];
    float f0 = (float)l0, f1 = (float)l1;
    float m = fmaxf(f0, f1);
    float e0 = expf(f0 - m), e1 = expf(f1 - m);
    float inv = 1.f / (e0 + e1);
    out[g * 2 + 0] = e0 * inv;
    out[g * 2 + 1] = e1 * inv;
}

// ---------------- launch ----------------
extern "C" void kernel_launch(void* const* d_in, const int* in_sizes, int n_in,
                              void* d_out, int out_size)
{
    const int*   node_ids = (const int*)d_in[0];
    const int*   edge     = (const int*)d_in[1];
    const int*   batch    = (const int*)d_in[2];
    const float* emb      = (const float*)d_in[3];
    const float* fh_W1 = (const float*)d_in[4];
    const float* fh_b1 = (const float*)d_in[5];
    const float* fh_g1 = (const float*)d_in[6];
    const float* fh_bt1 = (const float*)d_in[7];
    const float* fh_m1 = (const float*)d_in[8];
    const float* fh_v1 = (const float*)d_in[9];
    const float* fh_W2 = (const float*)d_in[10];
    const float* fh_b2 = (const float*)d_in[11];
    const float* fh_g2 = (const float*)d_in[12];
    const float* fh_bt2 = (const float*)d_in[13];
    const float* fh_m2 = (const float*)d_in[14];
    const float* fh_v2 = (const float*)d_in[15];
    const float* conv_W1 = (const float*)d_in[16];
    const float* conv_b1 = (const float*)d_in[17];
    const float* conv_g1 = (const float*)d_in[18];
    const float* conv_bt1 = (const float*)d_in[19];
    const float* conv_m1 = (const float*)d_in[20];
    const float* conv_v1 = (const float*)d_in[21];
    const float* conv_W2 = (const float*)d_in[22];
    const float* conv_b2 = (const float*)d_in[23];
    const float* conv_g2 = (const float*)d_in[24];
    const float* conv_bt2 = (const float*)d_in[25];
    const float* conv_m2 = (const float*)d_in[26];
    const float* conv_v2 = (const float*)d_in[27];
    const float* lin_W = (const float*)d_in[28];
    const float* lin_b = (const float*)d_in[29];

    int N = in_sizes[0];
    int E = in_sizes[1] / 2;
    int G = out_size / 2;
    const int* src = edge;
    const int* dst = edge + E;

    const int SMEM_EMB  = (128 * 64 + 64 * 64 + 128 * 68 + 64 * 68 + 256) * 4;  // 102400
    const int SMEM_CONV = (64 * 64 + 64 * 64 + 64 * 68 + 64 * 68 + 256) * 4;    // 68608
    cudaFuncSetAttribute((const void*)k_mlp<128, true>,
                         cudaFuncAttributeMaxDynamicSharedMemorySize, SMEM_EMB);
    cudaFuncSetAttribute((const void*)k_mlp<64, false>,
                         cudaFuncAttributeMaxDynamicSharedMemorySize, SMEM_CONV);

    // zero accumulators + degree counters
    int zn = (4 * MAXG * HDIM > N + 1) ? 4 * MAXG * HDIM : N + 1;
    k_zero<<<(zn + 255) / 256, 256>>>(N + 1);

    // CSR build (reused for all 3 conv layers)
    k_count<<<(E + 255) / 256, 256>>>(dst, E);
    int nb = (N + 1023) / 1024;
    k_scan1<<<nb, 1024>>>(N);
    k_scan2<<<1, 1024>>>(nb);
    k_scan3<<<(N + 255) / 256, 256>>>(N, nb);
    k_fill<<<(E + 255) / 256, 256>>>(src, dst, E);
    k_cnt<<<(N + 255) / 256, 256>>>(batch, N);

    int mblocks = (N + 63) / 64;

    // embedding gather + feature MLP + pool[0]
    k_mlp<128, true><<<mblocks, 256, SMEM_EMB>>>(
        emb, node_ids,
        fh_W1, fh_b1, fh_g1, fh_bt1, fh_m1, fh_v1,
        fh_W2, fh_b2, fh_g2, fh_bt2, fh_m2, fh_v2,
        batch, 0, N);

    // 3 GINConv layers
    for (int l = 0; l < 3; l++) {
        k_agg<<<(N + 7) / 8, 256>>>(N);
        k_mlp<64, false><<<mblocks, 256, SMEM_CONV>>>(
            nullptr, nullptr,
            conv_W1 + l * 4096, conv_b1 + l * 64, conv_g1 + l * 64, conv_bt1 + l * 64,
            conv_m1 + l * 64, conv_v1 + l * 64,
            conv_W2 + l * 4096, conv_b2 + l * 64, conv_g2 + l * 64, conv_bt2 + l * 64,
            conv_m2 + l * 64, conv_v2 + l * 64,
            batch, l + 1, N);
    }

    k_final<<<1, 128>>>(lin_W, lin_b, (float*)d_out, G);
}